// round 7
// baseline (speedup 1.0000x reference)
#include <cuda_runtime.h>
#include <cuda_fp16.h>
#include <cstdint>

// ---------------------------------------------------------------------------
// CompressedLinear:
//   out[s,o] = sum_i x[s,i] * (int8 W[o,i] * scale[o]) + bias[o]
//   x: [2048,4096] fp32   W: [11008,4096] delivered as INT32 (harness promotes
//   int8 -> int32; dtype map has no int8)   scale,bias: [11008] fp32   out fp32
//
// conv passes: x -> fp16, W*scale -> fp16 into __device__ scratch, then a
// mma.sync.m16n8k16 (fp16 in, fp32 accum) GEMM:
//   CTA tile 128x256x64, 3-stage cp.async pipeline, 8 warps (2x4), 64x64/warp,
//   128B XOR-swizzled smem, ldmatrix.x4 fragments, float2 epilogue + bias.
// ---------------------------------------------------------------------------

namespace {
constexpr int SEQ  = 2048;
constexpr int INF  = 4096;   // K
constexpr int OUTF = 11008;  // N

constexpr int BM = 128, BN = 256, BK = 64;
constexpr int KT_ITERS = INF / BK;        // 64
constexpr int NSTAGE   = 3;
constexpr uint32_t A_STAGE_BYTES = BM * 128u;           // 16384
constexpr uint32_t B_STAGE_BYTES = BN * 128u;           // 32768
constexpr uint32_t STAGE_BYTES   = A_STAGE_BYTES + B_STAGE_BYTES;  // 49152
constexpr uint32_t SMEM_BYTES    = NSTAGE * STAGE_BYTES;           // 147456
constexpr int GRID_M = SEQ / BM;          // 16
constexpr int GRID_N = OUTF / BN;         // 43
}

// Scratch (allocation-free rule: __device__ globals)
__device__ __half g_xh[SEQ * INF];                 // 16.8 MB
__device__ __half g_wh[(long long)OUTF * INF];     // 90.2 MB

// ------------------------------ PTX helpers --------------------------------

__device__ __forceinline__ uint32_t smem_u32(const void* p) {
    uint32_t a;
    asm("{ .reg .u64 t; cvta.to.shared.u64 t, %1; cvt.u32.u64 %0, t; }"
        : "=r"(a) : "l"(p));
    return a;
}

#define CP_ASYNC16(dst, src) \
    asm volatile("cp.async.cg.shared.global [%0], [%1], 16;" :: "r"(dst), "l"(src) : "memory")

#define CP_COMMIT() asm volatile("cp.async.commit_group;" ::: "memory")
#define CP_WAIT1()  asm volatile("cp.async.wait_group 1;" ::: "memory")

__device__ __forceinline__ void ldsm_x4(uint32_t (&r)[4], uint32_t addr) {
    asm volatile("ldmatrix.sync.aligned.m8n8.x4.shared.b16 {%0,%1,%2,%3}, [%4];"
                 : "=r"(r[0]), "=r"(r[1]), "=r"(r[2]), "=r"(r[3]) : "r"(addr));
}

__device__ __forceinline__ void mma16816(float (&d)[4], const uint32_t (&a)[4],
                                         uint32_t b0, uint32_t b1) {
    asm volatile(
        "mma.sync.aligned.m16n8k16.row.col.f32.f16.f16.f32 "
        "{%0,%1,%2,%3}, {%4,%5,%6,%7}, {%8,%9}, {%0,%1,%2,%3};"
        : "+f"(d[0]), "+f"(d[1]), "+f"(d[2]), "+f"(d[3])
        : "r"(a[0]), "r"(a[1]), "r"(a[2]), "r"(a[3]), "r"(b0), "r"(b1));
}

// --------------------------- conversion kernels ----------------------------

__global__ __launch_bounds__(256) void conv_x_kernel(const float* __restrict__ x) {
    int i = (blockIdx.x * 256 + threadIdx.x) * 4;   // 4 floats / thread, exact cover
    float4 v = *reinterpret_cast<const float4*>(x + i);
    __half2 a = __floats2half2_rn(v.x, v.y);
    __half2 b = __floats2half2_rn(v.z, v.w);
    uint2 o;
    o.x = *reinterpret_cast<uint32_t*>(&a);
    o.y = *reinterpret_cast<uint32_t*>(&b);
    *reinterpret_cast<uint2*>(g_xh + i) = o;
}

// Weight arrives as INT32 (one int8 value per 32-bit word).
__global__ __launch_bounds__(256) void conv_w_kernel(const int* __restrict__ w,
                                                     const float* __restrict__ scale) {
    int row = blockIdx.x;                 // 11008 rows
    int t   = threadIdx.x;                // 256 threads * 16 elements = 4096
    float s = __ldg(scale + row);
    size_t base = (size_t)row * INF + t * 16;
    __align__(16) __half h[16];
#pragma unroll
    for (int j = 0; j < 4; j++) {
        int4 v = *reinterpret_cast<const int4*>(w + base + j * 4);
        h[j * 4 + 0] = __float2half_rn((float)v.x * s);
        h[j * 4 + 1] = __float2half_rn((float)v.y * s);
        h[j * 4 + 2] = __float2half_rn((float)v.z * s);
        h[j * 4 + 3] = __float2half_rn((float)v.w * s);
    }
    *reinterpret_cast<uint4*>(g_wh + base)     = *reinterpret_cast<uint4*>(h);
    *reinterpret_cast<uint4*>(g_wh + base + 8) = *reinterpret_cast<uint4*>(h + 8);
}

// -------------------------------- GEMM kernel ------------------------------
//
// smem stage layout (per stage, 128B-swizzled K-major rows):
//   A: BM rows x 128B   (row = m, 8 chunks of 16B, chunk' = chunk ^ (row&7))
//   B: BN rows x 128B   (row = n)

__global__ __launch_bounds__(256, 1) void gemm_kernel(const float* __restrict__ bias,
                                                      float* __restrict__ out) {
    extern __shared__ __align__(128) char smem_raw[];
    const uint32_t sb = smem_u32(smem_raw);

    const int tid  = threadIdx.x;
    const int wid  = tid >> 5;
    const int lane = tid & 31;
    const int wm   = wid >> 2;            // 0..1 : 64-row warp tile
    const int wn   = wid & 3;             // 0..3 : 64-col warp tile

    const int bid = blockIdx.x;
    const int m0  = (bid & 15) * BM;      // m fastest -> B tile L2 reuse x16
    const int n0  = (bid >> 4) * BN;

    // loader constants: A 1024 16B-chunks (4/thread), B 2048 (8/thread)
    const int l_row0  = tid >> 3;                  // rows l_row0 + 32*i
    const int l_chunk = tid & 7;

    // ldmatrix lane math (fragment contracts verified)
    const int a_ld_row = wm * 64 + (lane & 15);    // + mf*16
    const int a_ld_hi  = lane >> 4;                // chunk low bit
    const int b_ld_row = wn * 64 + (lane & 7) + ((lane >> 4) & 1) * 8;  // + nf2*16
    const int b_ld_hi  = (lane >> 3) & 1;

    float acc[4][8][4];
#pragma unroll
    for (int i = 0; i < 4; i++)
#pragma unroll
        for (int j = 0; j < 8; j++)
#pragma unroll
            for (int k = 0; k < 4; k++) acc[i][j][k] = 0.0f;

    const __half* __restrict__ Asrc = g_xh + (size_t)m0 * INF;
    const __half* __restrict__ Bsrc = g_wh + (size_t)n0 * INF;

    auto issue_stage = [&](int kt, int s) {
        const uint32_t ab = sb + (uint32_t)s * STAGE_BYTES;
        const uint32_t bb = ab + A_STAGE_BYTES;
        const int kk = kt * BK;
#pragma unroll
        for (int i = 0; i < 4; i++) {
            const int row = l_row0 + i * 32;
            const uint32_t dst = ab + (uint32_t)(row * 128) +
                                 (uint32_t)((l_chunk ^ (row & 7)) << 4);
            CP_ASYNC16(dst, Asrc + (size_t)row * INF + kk + l_chunk * 8);
        }
#pragma unroll
        for (int i = 0; i < 8; i++) {
            const int row = l_row0 + i * 32;
            const uint32_t dst = bb + (uint32_t)(row * 128) +
                                 (uint32_t)((l_chunk ^ (row & 7)) << 4);
            CP_ASYNC16(dst, Bsrc + (size_t)row * INF + kk + l_chunk * 8);
        }
    };

    // ---- prologue: stages 0,1 --------------------------------------------
    issue_stage(0, 0); CP_COMMIT();
    issue_stage(1, 1); CP_COMMIT();

    int stage = 0;
#pragma unroll 1
    for (int kt = 0; kt < KT_ITERS; ++kt) {
        CP_WAIT1();                 // stage kt resident (<=1 newer group pending)
        __syncthreads();            // visibility + stage (kt+2)%3 slot free
        if (kt + 2 < KT_ITERS) issue_stage(kt + 2, (kt + 2) % NSTAGE);
        CP_COMMIT();

        const uint32_t ab = sb + (uint32_t)stage * STAGE_BYTES;
        const uint32_t bb = ab + A_STAGE_BYTES;

#pragma unroll
        for (int s = 0; s < 4; s++) {          // 4 x k16 per BK=64 stage
            uint32_t afr[4][4];
#pragma unroll
            for (int mf = 0; mf < 4; mf++) {
                const int row = a_ld_row + mf * 16;
                const int ch  = 2 * s + a_ld_hi;
                ldsm_x4(afr[mf], ab + (uint32_t)(row * 128) +
                                  (uint32_t)((ch ^ (row & 7)) << 4));
            }
            uint32_t bfr[4][4];
#pragma unroll
            for (int nf2 = 0; nf2 < 4; nf2++) {
                const int row = b_ld_row + nf2 * 16;
                const int ch  = 2 * s + b_ld_hi;
                ldsm_x4(bfr[nf2], bb + (uint32_t)(row * 128) +
                                   (uint32_t)((ch ^ (row & 7)) << 4));
            }
#pragma unroll
            for (int mf = 0; mf < 4; mf++)
#pragma unroll
                for (int nf = 0; nf < 8; nf++)
                    mma16816(acc[mf][nf], afr[mf],
                             bfr[nf >> 1][(nf & 1) * 2],
                             bfr[nf >> 1][(nf & 1) * 2 + 1]);
        }

        __syncthreads();            // all warps done with stage before reuse
        if (++stage == NSTAGE) stage = 0;
    }

    // ------------------------------- epilogue ------------------------------
    const int mwarp = m0 + wm * 64 + (lane >> 2);
    const int nwarp = n0 + wn * 64 + (lane & 3) * 2;

    float2 bv[8];
#pragma unroll
    for (int nf = 0; nf < 8; nf++)
        bv[nf] = *reinterpret_cast<const float2*>(bias + nwarp + nf * 8);

#pragma unroll
    for (int mf = 0; mf < 4; mf++) {
        const int m = mwarp + mf * 16;
#pragma unroll
        for (int nf = 0; nf < 8; nf++) {
            const int n = nwarp + nf * 8;
            float2 o0 = {acc[mf][nf][0] + bv[nf].x, acc[mf][nf][1] + bv[nf].y};
            float2 o1 = {acc[mf][nf][2] + bv[nf].x, acc[mf][nf][3] + bv[nf].y};
            *reinterpret_cast<float2*>(out + (size_t)m * OUTF + n)       = o0;
            *reinterpret_cast<float2*>(out + (size_t)(m + 8) * OUTF + n) = o1;
        }
    }
}

// ------------------------------- launch ------------------------------------

extern "C" void kernel_launch(void* const* d_in, const int* in_sizes, int n_in,
                              void* d_out, int out_size) {
    (void)out_size;
    // Identify inputs robustly by element count; scale/bias keep relative order.
    const float* x     = nullptr;
    const int*   w32   = nullptr;   // int8 weights promoted to int32 by harness
    const float* scale = nullptr;
    const float* bias  = nullptr;
    for (int i = 0; i < n_in; i++) {
        if (in_sizes[i] == SEQ * INF)            x   = (const float*)d_in[i];
        else if (in_sizes[i] == OUTF * INF)      w32 = (const int*)d_in[i];
        else if (in_sizes[i] == OUTF) {
            if (!scale) scale = (const float*)d_in[i];
            else        bias  = (const float*)d_in[i];
        }
    }
    float* out = (float*)d_out;

    cudaFuncSetAttribute(gemm_kernel, cudaFuncAttributeMaxDynamicSharedMemorySize,
                         (int)SMEM_BYTES);

    conv_x_kernel<<<(SEQ * INF) / (256 * 4), 256>>>(x);
    conv_w_kernel<<<OUTF, 256>>>(w32, scale);
    gemm_kernel<<<GRID_M * GRID_N, 256, SMEM_BYTES>>>(bias, out);
}

// round 9
// speedup vs baseline: 1.0085x; 1.0085x over previous
#include <cuda_runtime.h>
#include <cuda_fp16.h>
#include <cstdint>

// ---------------------------------------------------------------------------
// CompressedLinear:
//   out[s,o] = sum_i x[s,i] * (int8 W[o,i] * scale[o]) + bias[o]
//   x: [2048,4096] fp32   W: [11008,4096] delivered as INT32 (harness promotes
//   int8 -> int32)   scale,bias: [11008] fp32   out: [2048,11008] fp32
//
// conv passes: x -> fp16, W*scale -> fp16 into __device__ scratch, then a
// mma.sync.m16n8k16 (fp16 in, fp32 accum) GEMM:
//   CTA tile 128x256x64, 4-stage cp.async pipeline (single sync/iter),
//   8 warps (2x4), 64x64/warp, 128B XOR-swizzled smem, ldmatrix.x4.
// ---------------------------------------------------------------------------

namespace {
constexpr int SEQ  = 2048;
constexpr int INF  = 4096;   // K
constexpr int OUTF = 11008;  // N

constexpr int BM = 128, BN = 256, BK = 64;
constexpr int KT_ITERS = INF / BK;        // 64
constexpr int NSTAGE   = 4;
constexpr uint32_t A_STAGE_BYTES = BM * 128u;           // 16384
constexpr uint32_t B_STAGE_BYTES = BN * 128u;           // 32768
constexpr uint32_t STAGE_BYTES   = A_STAGE_BYTES + B_STAGE_BYTES;  // 49152
constexpr uint32_t SMEM_BYTES    = NSTAGE * STAGE_BYTES;           // 196608
constexpr int GRID_M = SEQ / BM;          // 16
constexpr int GRID_N = OUTF / BN;         // 43
}

// Scratch (allocation-free rule: __device__ globals)
__device__ __half g_xh[SEQ * INF];                 // 16.8 MB
__device__ __half g_wh[(long long)OUTF * INF];     // 90.2 MB

// ------------------------------ PTX helpers --------------------------------

__device__ __forceinline__ uint32_t smem_u32(const void* p) {
    uint32_t a;
    asm("{ .reg .u64 t; cvta.to.shared.u64 t, %1; cvt.u32.u64 %0, t; }"
        : "=r"(a) : "l"(p));
    return a;
}

#define CP_ASYNC16(dst, src) \
    asm volatile("cp.async.cg.shared.global [%0], [%1], 16;" :: "r"(dst), "l"(src) : "memory")

#define CP_COMMIT() asm volatile("cp.async.commit_group;" ::: "memory")
#define CP_WAIT2()  asm volatile("cp.async.wait_group 2;" ::: "memory")

__device__ __forceinline__ void ldsm_x4(uint32_t (&r)[4], uint32_t addr) {
    asm volatile("ldmatrix.sync.aligned.m8n8.x4.shared.b16 {%0,%1,%2,%3}, [%4];"
                 : "=r"(r[0]), "=r"(r[1]), "=r"(r[2]), "=r"(r[3]) : "r"(addr));
}

__device__ __forceinline__ void mma16816(float (&d)[4], const uint32_t (&a)[4],
                                         uint32_t b0, uint32_t b1) {
    asm volatile(
        "mma.sync.aligned.m16n8k16.row.col.f32.f16.f16.f32 "
        "{%0,%1,%2,%3}, {%4,%5,%6,%7}, {%8,%9}, {%0,%1,%2,%3};"
        : "+f"(d[0]), "+f"(d[1]), "+f"(d[2]), "+f"(d[3])
        : "r"(a[0]), "r"(a[1]), "r"(a[2]), "r"(a[3]), "r"(b0), "r"(b1));
}

// --------------------------- conversion kernels ----------------------------

__global__ __launch_bounds__(256) void conv_x_kernel(const float* __restrict__ x) {
    int i = (blockIdx.x * 256 + threadIdx.x) * 4;   // 4 floats / thread, exact cover
    float4 v = *reinterpret_cast<const float4*>(x + i);
    __half2 a = __floats2half2_rn(v.x, v.y);
    __half2 b = __floats2half2_rn(v.z, v.w);
    uint2 o;
    o.x = *reinterpret_cast<uint32_t*>(&a);
    o.y = *reinterpret_cast<uint32_t*>(&b);
    *reinterpret_cast<uint2*>(g_xh + i) = o;
}

// Weight arrives as INT32 (one int8 value per 32-bit word).
__global__ __launch_bounds__(256) void conv_w_kernel(const int* __restrict__ w,
                                                     const float* __restrict__ scale) {
    int row = blockIdx.x;                 // 11008 rows
    int t   = threadIdx.x;                // 256 threads * 16 elements = 4096
    float s = __ldg(scale + row);
    size_t base = (size_t)row * INF + t * 16;
    __align__(16) __half h[16];
#pragma unroll
    for (int j = 0; j < 4; j++) {
        int4 v = *reinterpret_cast<const int4*>(w + base + j * 4);
        h[j * 4 + 0] = __float2half_rn((float)v.x * s);
        h[j * 4 + 1] = __float2half_rn((float)v.y * s);
        h[j * 4 + 2] = __float2half_rn((float)v.z * s);
        h[j * 4 + 3] = __float2half_rn((float)v.w * s);
    }
    *reinterpret_cast<uint4*>(g_wh + base)     = *reinterpret_cast<uint4*>(h);
    *reinterpret_cast<uint4*>(g_wh + base + 8) = *reinterpret_cast<uint4*>(h + 8);
}

// -------------------------------- GEMM kernel ------------------------------
//
// smem stage layout (per stage, 128B-swizzled K-major rows):
//   A: BM rows x 128B   (row = m, 8 chunks of 16B, chunk' = chunk ^ (row&7))
//   B: BN rows x 128B   (row = n)
//
// Pipeline invariant (single sync per iteration): at the top of iteration kt,
// wait_group 2 makes stage kt resident; the sync then (a) publishes it to all
// warps and (b) guarantees every warp finished reading slot (kt+3)%4 == slot
// of iteration kt-1, so the subsequent issue for tile kt+3 into that slot is
// race-free.

__global__ __launch_bounds__(256, 1) void gemm_kernel(const float* __restrict__ bias,
                                                      float* __restrict__ out) {
    extern __shared__ __align__(128) char smem_raw[];
    const uint32_t sb = smem_u32(smem_raw);

    const int tid  = threadIdx.x;
    const int lane = tid & 31;
    const int wid  = tid >> 5;
    const int wm   = wid >> 2;            // 0..1 : 64-row warp tile
    const int wn   = wid & 3;             // 0..3 : 64-col warp tile

    const int bid = blockIdx.x;
    const int m0  = (bid & 15) * BM;      // m fastest -> B tile L2 reuse x16
    const int n0  = (bid >> 4) * BN;

    // loader constants: A 1024 16B-chunks (4/thread), B 2048 (8/thread)
    const int l_row0  = tid >> 3;                  // rows l_row0 + 32*i
    const int l_chunk = tid & 7;

    // ldmatrix lane math (fragment contracts verified)
    const int a_ld_row = wm * 64 + (lane & 15);    // + mf*16
    const int a_ld_hi  = lane >> 4;                // chunk low bit
    const int b_ld_row = wn * 64 + (lane & 7) + ((lane >> 4) & 1) * 8;  // + nf2*16
    const int b_ld_hi  = (lane >> 3) & 1;

    float acc[4][8][4];
#pragma unroll
    for (int i = 0; i < 4; i++)
#pragma unroll
        for (int j = 0; j < 8; j++)
#pragma unroll
            for (int k = 0; k < 4; k++) acc[i][j][k] = 0.0f;

    const __half* __restrict__ Asrc = g_xh + (size_t)m0 * INF;
    const __half* __restrict__ Bsrc = g_wh + (size_t)n0 * INF;

    auto issue_stage = [&](int kt, int s) {
        const uint32_t ab = sb + (uint32_t)s * STAGE_BYTES;
        const uint32_t bb = ab + A_STAGE_BYTES;
        const int kk = kt * BK;
#pragma unroll
        for (int i = 0; i < 4; i++) {
            const int row = l_row0 + i * 32;
            const uint32_t dst = ab + (uint32_t)(row * 128) +
                                 (uint32_t)((l_chunk ^ (row & 7)) << 4);
            CP_ASYNC16(dst, Asrc + (size_t)row * INF + kk + l_chunk * 8);
        }
#pragma unroll
        for (int i = 0; i < 8; i++) {
            const int row = l_row0 + i * 32;
            const uint32_t dst = bb + (uint32_t)(row * 128) +
                                 (uint32_t)((l_chunk ^ (row & 7)) << 4);
            CP_ASYNC16(dst, Bsrc + (size_t)row * INF + kk + l_chunk * 8);
        }
    };

    // ---- prologue: fill NSTAGE-1 = 3 stages ------------------------------
    issue_stage(0, 0); CP_COMMIT();
    issue_stage(1, 1); CP_COMMIT();
    issue_stage(2, 2); CP_COMMIT();

    int stage = 0;
#pragma unroll 1
    for (int kt = 0; kt < KT_ITERS; ++kt) {
        CP_WAIT2();                 // stage kt resident (<=2 newer groups pending)
        __syncthreads();            // publish + slot (kt+3)%4 reusable

        if (kt + 3 < KT_ITERS) issue_stage(kt + 3, (kt + 3) % NSTAGE);
        CP_COMMIT();

        const uint32_t ab = sb + (uint32_t)stage * STAGE_BYTES;
        const uint32_t bb = ab + A_STAGE_BYTES;

#pragma unroll
        for (int s = 0; s < 4; s++) {          // 4 x k16 per BK=64 stage
            uint32_t afr[4][4];
#pragma unroll
            for (int mf = 0; mf < 4; mf++) {
                const int row = a_ld_row + mf * 16;
                const int ch  = 2 * s + a_ld_hi;
                ldsm_x4(afr[mf], ab + (uint32_t)(row * 128) +
                                  (uint32_t)((ch ^ (row & 7)) << 4));
            }
            uint32_t bfr[4][4];
#pragma unroll
            for (int nf2 = 0; nf2 < 4; nf2++) {
                const int row = b_ld_row + nf2 * 16;
                const int ch  = 2 * s + b_ld_hi;
                ldsm_x4(bfr[nf2], bb + (uint32_t)(row * 128) +
                                   (uint32_t)((ch ^ (row & 7)) << 4));
            }
#pragma unroll
            for (int mf = 0; mf < 4; mf++)
#pragma unroll
                for (int nf = 0; nf < 8; nf++)
                    mma16816(acc[mf][nf], afr[mf],
                             bfr[nf >> 1][(nf & 1) * 2],
                             bfr[nf >> 1][(nf & 1) * 2 + 1]);
        }

        if (++stage == NSTAGE) stage = 0;
    }

    // ------------------------------- epilogue ------------------------------
    const int mwarp = m0 + wm * 64 + (lane >> 2);
    const int nwarp = n0 + wn * 64 + (lane & 3) * 2;

    float2 bv[8];
#pragma unroll
    for (int nf = 0; nf < 8; nf++)
        bv[nf] = *reinterpret_cast<const float2*>(bias + nwarp + nf * 8);

#pragma unroll
    for (int mf = 0; mf < 4; mf++) {
        const int m = mwarp + mf * 16;
#pragma unroll
        for (int nf = 0; nf < 8; nf++) {
            const int n = nwarp + nf * 8;
            float2 o0 = {acc[mf][nf][0] + bv[nf].x, acc[mf][nf][1] + bv[nf].y};
            float2 o1 = {acc[mf][nf][2] + bv[nf].x, acc[mf][nf][3] + bv[nf].y};
            *reinterpret_cast<float2*>(out + (size_t)m * OUTF + n)       = o0;
            *reinterpret_cast<float2*>(out + (size_t)(m + 8) * OUTF + n) = o1;
        }
    }
}

// ------------------------------- launch ------------------------------------

extern "C" void kernel_launch(void* const* d_in, const int* in_sizes, int n_in,
                              void* d_out, int out_size) {
    (void)out_size;
    // Identify inputs robustly by element count; scale/bias keep relative order.
    const float* x     = nullptr;
    const int*   w32   = nullptr;   // int8 weights promoted to int32 by harness
    const float* scale = nullptr;
    const float* bias  = nullptr;
    for (int i = 0; i < n_in; i++) {
        if (in_sizes[i] == SEQ * INF)            x   = (const float*)d_in[i];
        else if (in_sizes[i] == OUTF * INF)      w32 = (const int*)d_in[i];
        else if (in_sizes[i] == OUTF) {
            if (!scale) scale = (const float*)d_in[i];
            else        bias  = (const float*)d_in[i];
        }
    }
    float* out = (float*)d_out;

    cudaFuncSetAttribute(gemm_kernel, cudaFuncAttributeMaxDynamicSharedMemorySize,
                         (int)SMEM_BYTES);

    conv_x_kernel<<<(SEQ * INF) / (256 * 4), 256>>>(x);
    conv_w_kernel<<<OUTF, 256>>>(w32, scale);
    gemm_kernel<<<GRID_M * GRID_N, 256, SMEM_BYTES>>>(bias, out);
}